// round 6
// baseline (speedup 1.0000x reference)
#include <cuda_runtime.h>
#include <cuda_bf16.h>
#include <cstdint>

// yolo_v3 detection head:
//   in : x [B, 255, 64, 64] f32, anchors [3,2] f32
//   out: [B, 4096*3, 85] f32
// out[b, s*255 + r] = f(x[b, r, s]),  r = a*85+d:
//   d==0: (sigmoid(v) + s%64) * 8
//   d==1: (sigmoid(v) + s/64) * 8
//   d==2,3: exp(v) * anchors[a][d-2]   (stride factors cancel)
//   d>=4: sigmoid(v)
// Unified: e=exp(v); res = e * 1/(1+ne*e) * scale + off

#define S_DIM 64
#define WH    4096
#define NA    3
#define ND    85
#define NC    255
#define TS    32                    // s-values per block
#define NTHREADS 512
#define NITEMS (NC * (TS / 4))      // 2040 float4 items
#define TILE_BYTES (TS * NC * 4)    // 32640 B == output slab for this block

__global__ __launch_bounds__(NTHREADS)
void yolo_head_kernel(const float* __restrict__ x,
                      const float* __restrict__ anchors,
                      float* __restrict__ out)
{
    __shared__ __align__(16) float tile[TS * NC];   // output-layout tile

    const int s0  = blockIdx.x * TS;
    const int b   = blockIdx.y;
    const int tid = threadIdx.x;

    const float fxb8 = 8.0f * (float)(s0 & (S_DIM - 1));  // s0%64 in {0,32}; sl<32
    const float fyb8 = 8.0f * (float)(s0 >> 6);           // constant within block

    // ---- Phase 1: load float4 along s, transform, scatter into output-layout tile ----
    const float4* __restrict__ xin =
        reinterpret_cast<const float4*>(x + (size_t)b * NC * WH + s0);

    #pragma unroll
    for (int k = 0; k < 4; k++) {
        int i = tid + k * NTHREADS;
        if (i < NITEMS) {
            int c = i >> 3;                 // channel 0..254
            int q = i & 7;                  // float4 index within 32-wide row
            float4 v = xin[c * (WH / 4) + q];

            // channel params, division-free (c < 255)
            int a = (c >= 2 * ND) ? 2 : (c >= ND ? 1 : 0);
            int d = c - a * ND;
            float ne = 1.0f, scale = 1.0f, offbase = 0.0f, offstep = 0.0f;
            if (d == 0)      { scale = 8.0f; offbase = fmaf(32.0f, (float)q, fxb8); offstep = 8.0f; }
            else if (d == 1) { scale = 8.0f; offbase = fyb8; }
            else if (d < 4)  { ne = 0.0f; scale = __ldg(&anchors[a * 2 + (d - 2)]); }

            float vv[4] = {v.x, v.y, v.z, v.w};
            float* dst = &tile[(q * 4) * NC + c];
            #pragma unroll
            for (int j = 0; j < 4; j++) {
                float e = __expf(vv[j]);
                float t = __fdividef(1.0f, fmaf(e, ne, 1.0f));
                dst[j * NC] = fmaf(e * t, scale, fmaf(offstep, (float)j, offbase));
            }
        }
    }

    __syncthreads();

    // ---- Phase 2: one bulk DMA copy smem -> gmem (tile layout == output slab) ----
    if (tid == 0) {
        asm volatile("fence.proxy.async.shared::cta;" ::: "memory");
        float* gdst = out + (size_t)b * WH * NC + (size_t)s0 * NC;
        uint32_t saddr;
        asm("{ .reg .u64 t; cvta.to.shared.u64 t, %1; cvt.u32.u64 %0, t; }"
            : "=r"(saddr) : "l"(tile));
        uint32_t nbytes = TILE_BYTES;
        asm volatile(
            "cp.async.bulk.global.shared::cta.bulk_group [%0], [%1], %2;"
            :: "l"(gdst), "r"(saddr), "r"(nbytes) : "memory");
        asm volatile("cp.async.bulk.commit_group;" ::: "memory");
        asm volatile("cp.async.bulk.wait_group 0;" ::: "memory");
    }
}

extern "C" void kernel_launch(void* const* d_in, const int* in_sizes, int n_in,
                              void* d_out, int out_size)
{
    const float* x       = (const float*)d_in[0];
    const float* anchors = (const float*)d_in[1];
    float* out           = (float*)d_out;

    int B = in_sizes[0] / (NC * WH);
    dim3 grid(WH / TS, B);
    yolo_head_kernel<<<grid, NTHREADS>>>(x, anchors, out);
}